// round 3
// baseline (speedup 1.0000x reference)
#include <cuda_runtime.h>

// Problem dims
#define MTOT   16384      // BATCH*T = 8*2048
#define NN     512
#define TSEQ   2048
#define NBATCH 8
#define NCHUNK 32
#define CHUNKT 64

// Scratch (no allocations allowed -> __device__ globals)
__device__ float g_xre[(size_t)MTOT * NN];   // GEMM1 out (new_u re) -> scan in place -> x_re
__device__ float g_xim[(size_t)MTOT * NN];
__device__ float g_cre[NBATCH * NCHUNK * NN];  // chunk carries
__device__ float g_cim[NBATCH * NCHUNK * NN];
__device__ float g_pre[NBATCH * NCHUNK * NN];  // inclusive chunk prefixes
__device__ float g_pim[NBATCH * NCHUNK * NN];

// ---- packed f32x2 helpers (FFMA2: 2 fp32 FMAs per instruction) ----
__device__ __forceinline__ unsigned long long pack2(float x, float y) {
    unsigned long long r;
    asm("mov.b64 %0, {%1, %2};" : "=l"(r) : "f"(x), "f"(y));
    return r;
}
__device__ __forceinline__ void unpack2(unsigned long long v, float &x, float &y) {
    asm("mov.b64 {%0, %1}, %2;" : "=f"(x), "=f"(y) : "l"(v));
}
__device__ __forceinline__ void fma2(unsigned long long &d, unsigned long long a,
                                     unsigned long long b) {
    asm("fma.rn.f32x2 %0, %1, %2, %0;" : "+l"(d) : "l"(a), "l"(b));
}

// ============================================================================
// GEMM1: g_xre = (u*gamma) @ B_re ; g_xim = (u*gamma) @ B_im
// gamma folded into B rows. Tiles: BM=128, BN=64, BK=16; 256 thr; 8x4 microtile.
// ============================================================================
__global__ __launch_bounds__(256) void gemm1_kernel(
    const float* __restrict__ u, const float* __restrict__ Bre,
    const float* __restrict__ Bim, const float* __restrict__ gamma)
{
    __shared__ float As[16][128];
    __shared__ float Bsr[16][64];
    __shared__ float Bsi[16][64];
    const int tid = threadIdx.x;
    const int tx = tid & 15, ty = tid >> 4;
    const int mBase = blockIdx.y * 128;
    const int nBase = blockIdx.x * 64;

    unsigned long long accR[8][2], accI[8][2];
    const unsigned long long z = pack2(0.f, 0.f);
#pragma unroll
    for (int i = 0; i < 8; i++) { accR[i][0]=z; accR[i][1]=z; accI[i][0]=z; accI[i][1]=z; }

    const int bk = tid >> 4;          // 0..15 : B tile row (k)
    const int bn = (tid & 15) << 2;   // 0..60 : B tile col

    for (int kt = 0; kt < 512; kt += 16) {
        // A tile: 128x16, transposed store As[k][m]
#pragma unroll
        for (int i = 0; i < 2; i++) {
            int idx = tid + i * 256;
            int m = idx >> 2, k4 = (idx & 3) << 2;
            float4 v = *(const float4*)&u[(size_t)(mBase + m) * 512 + kt + k4];
            As[k4 + 0][m] = v.x; As[k4 + 1][m] = v.y;
            As[k4 + 2][m] = v.z; As[k4 + 3][m] = v.w;
        }
        // B tiles scaled by gamma[k]
        {
            float g = gamma[kt + bk];
            float4 vr = *(const float4*)&Bre[(size_t)(kt + bk) * 512 + nBase + bn];
            float4 vi = *(const float4*)&Bim[(size_t)(kt + bk) * 512 + nBase + bn];
            *(float4*)&Bsr[bk][bn] = make_float4(vr.x*g, vr.y*g, vr.z*g, vr.w*g);
            *(float4*)&Bsi[bk][bn] = make_float4(vi.x*g, vi.y*g, vi.z*g, vi.w*g);
        }
        __syncthreads();
#pragma unroll
        for (int kk = 0; kk < 16; kk++) {
            float4 a0 = *(const float4*)&As[kk][ty * 8];
            float4 a1 = *(const float4*)&As[kk][ty * 8 + 4];
            const unsigned long long* bpr = (const unsigned long long*)&Bsr[kk][tx * 4];
            const unsigned long long* bpi = (const unsigned long long*)&Bsi[kk][tx * 4];
            unsigned long long br0 = bpr[0], br1 = bpr[1];
            unsigned long long bi0 = bpi[0], bi1 = bpi[1];
            float a[8] = {a0.x, a0.y, a0.z, a0.w, a1.x, a1.y, a1.z, a1.w};
#pragma unroll
            for (int i = 0; i < 8; i++) {
                unsigned long long ap = pack2(a[i], a[i]);
                fma2(accR[i][0], ap, br0); fma2(accR[i][1], ap, br1);
                fma2(accI[i][0], ap, bi0); fma2(accI[i][1], ap, bi1);
            }
        }
        __syncthreads();
    }
#pragma unroll
    for (int i = 0; i < 8; i++) {
        float r0,r1,r2,r3,s0,s1,s2,s3;
        unpack2(accR[i][0], r0, r1); unpack2(accR[i][1], r2, r3);
        unpack2(accI[i][0], s0, s1); unpack2(accI[i][1], s2, s3);
        size_t off = (size_t)(mBase + ty * 8 + i) * 512 + nBase + tx * 4;
        *(float4*)&g_xre[off] = make_float4(r0, r1, r2, r3);
        *(float4*)&g_xim[off] = make_float4(s0, s1, s2, s3);
    }
}

// ============================================================================
// Scan phase 1: per-chunk local scan (x[t] = lam*x[t-1] + new_u[t], x_in = 0),
// in place; store chunk-end carry.
// ============================================================================
__global__ __launch_bounds__(512) void scan_local_kernel(
    const float* __restrict__ nu, const float* __restrict__ theta)
{
    const int n = threadIdx.x;
    const int c = blockIdx.x;     // 0..31
    const int b = blockIdx.y;     // 0..7
    const float r   = expf(-expf(nu[n]));
    const float th  = theta[n];
    const float lre = r * cosf(th), lim = r * sinf(th);
    float xr = 0.f, xi = 0.f;
    size_t base = ((size_t)(b * TSEQ + c * CHUNKT)) * NN + n;
    for (int t = 0; t < CHUNKT; t++) {
        size_t idx = base + (size_t)t * NN;
        float ur = g_xre[idx], ui = g_xim[idx];
        float nr = lre * xr - lim * xi + ur;
        float ni = lre * xi + lim * xr + ui;
        xr = nr; xi = ni;
        g_xre[idx] = xr; g_xim[idx] = xi;
    }
    int coff = (b * NCHUNK + c) * NN + n;
    g_cre[coff] = xr; g_cim[coff] = xi;
}

// ============================================================================
// Scan phase 2: inclusive prefix over chunk carries: P[c] = lam^64 * P[c-1] + carry[c]
// ============================================================================
__global__ __launch_bounds__(512) void scan_chunk_kernel(
    const float* __restrict__ nu, const float* __restrict__ theta)
{
    const int n = threadIdx.x;
    const int b = blockIdx.x;
    const float e   = expf(nu[n]);
    const float rP  = expf(-(float)CHUNKT * e);
    const float ang = (float)CHUNKT * theta[n];
    const float Lre = rP * cosf(ang), Lim = rP * sinf(ang);
    float pr = 0.f, pi = 0.f;
    for (int c = 0; c < NCHUNK; c++) {
        int off = (b * NCHUNK + c) * NN + n;
        float cr = g_cre[off], ci = g_cim[off];
        float nr = Lre * pr - Lim * pi + cr;
        float ni = Lre * pi + Lim * pr + ci;
        pr = nr; pi = ni;
        g_pre[off] = pr; g_pim[off] = pi;
    }
}

// ============================================================================
// Scan phase 3: fixup chunks c>=1: x[t] += lam^{t-t0+1} * P[c-1]
// ============================================================================
__global__ __launch_bounds__(512) void scan_fix_kernel(
    const float* __restrict__ nu, const float* __restrict__ theta)
{
    const int n = threadIdx.x;
    const int c = blockIdx.x + 1;   // 1..31
    const int b = blockIdx.y;
    const float r   = expf(-expf(nu[n]));
    const float th  = theta[n];
    const float lre = r * cosf(th), lim = r * sinf(th);
    int poff = (b * NCHUNK + (c - 1)) * NN + n;
    float mr = g_pre[poff], mi = g_pim[poff];
    size_t base = ((size_t)(b * TSEQ + c * CHUNKT)) * NN + n;
    for (int t = 0; t < CHUNKT; t++) {
        float tr = lre * mr - lim * mi;
        float ti = lre * mi + lim * mr;
        mr = tr; mi = ti;
        size_t idx = base + (size_t)t * NN;
        g_xre[idx] += mr;
        g_xim[idx] += mi;
    }
}

// ============================================================================
// GEMM2: out = x_re@C_re - x_im@C_im + D*u
// C_im pre-negated at tile load so the inner loop is pure FMA2.
// ============================================================================
__global__ __launch_bounds__(256) void gemm2_kernel(
    const float* __restrict__ Cre, const float* __restrict__ Cim,
    const float* __restrict__ u, const float* __restrict__ D,
    float* __restrict__ out)
{
    __shared__ float As1[16][128];
    __shared__ float As2[16][128];
    __shared__ float Bs1[16][64];
    __shared__ float Bs2[16][64];   // holds -C_im
    const int tid = threadIdx.x;
    const int tx = tid & 15, ty = tid >> 4;
    const int mBase = blockIdx.y * 128;
    const int nBase = blockIdx.x * 64;

    unsigned long long acc[8][2];
    const unsigned long long z = pack2(0.f, 0.f);
#pragma unroll
    for (int i = 0; i < 8; i++) { acc[i][0] = z; acc[i][1] = z; }

    const int bk = tid >> 4;
    const int bn = (tid & 15) << 2;

    for (int kt = 0; kt < 512; kt += 16) {
#pragma unroll
        for (int i = 0; i < 2; i++) {
            int idx = tid + i * 256;
            int m = idx >> 2, k4 = (idx & 3) << 2;
            size_t goff = (size_t)(mBase + m) * 512 + kt + k4;
            float4 v1 = *(const float4*)&g_xre[goff];
            float4 v2 = *(const float4*)&g_xim[goff];
            As1[k4+0][m]=v1.x; As1[k4+1][m]=v1.y; As1[k4+2][m]=v1.z; As1[k4+3][m]=v1.w;
            As2[k4+0][m]=v2.x; As2[k4+1][m]=v2.y; As2[k4+2][m]=v2.z; As2[k4+3][m]=v2.w;
        }
        {
            float4 v1 = *(const float4*)&Cre[(size_t)(kt + bk) * 512 + nBase + bn];
            float4 v2 = *(const float4*)&Cim[(size_t)(kt + bk) * 512 + nBase + bn];
            *(float4*)&Bs1[bk][bn] = v1;
            *(float4*)&Bs2[bk][bn] = make_float4(-v2.x, -v2.y, -v2.z, -v2.w);
        }
        __syncthreads();
#pragma unroll
        for (int kk = 0; kk < 16; kk++) {
            float4 a10 = *(const float4*)&As1[kk][ty * 8];
            float4 a11 = *(const float4*)&As1[kk][ty * 8 + 4];
            float4 a20 = *(const float4*)&As2[kk][ty * 8];
            float4 a21 = *(const float4*)&As2[kk][ty * 8 + 4];
            const unsigned long long* bp1 = (const unsigned long long*)&Bs1[kk][tx * 4];
            const unsigned long long* bp2 = (const unsigned long long*)&Bs2[kk][tx * 4];
            unsigned long long b10 = bp1[0], b11 = bp1[1];
            unsigned long long b20 = bp2[0], b21 = bp2[1];
            float a1[8] = {a10.x,a10.y,a10.z,a10.w,a11.x,a11.y,a11.z,a11.w};
            float a2[8] = {a20.x,a20.y,a20.z,a20.w,a21.x,a21.y,a21.z,a21.w};
#pragma unroll
            for (int i = 0; i < 8; i++) {
                unsigned long long ap1 = pack2(a1[i], a1[i]);
                fma2(acc[i][0], ap1, b10); fma2(acc[i][1], ap1, b11);
                unsigned long long ap2 = pack2(a2[i], a2[i]);
                fma2(acc[i][0], ap2, b20); fma2(acc[i][1], ap2, b21);
            }
        }
        __syncthreads();
    }
    float4 d4 = *(const float4*)&D[nBase + tx * 4];
#pragma unroll
    for (int i = 0; i < 8; i++) {
        float y0,y1,y2,y3;
        unpack2(acc[i][0], y0, y1); unpack2(acc[i][1], y2, y3);
        size_t off = (size_t)(mBase + ty * 8 + i) * 512 + nBase + tx * 4;
        float4 uu = *(const float4*)&u[off];
        *(float4*)&out[off] = make_float4(y0 + d4.x * uu.x, y1 + d4.y * uu.y,
                                          y2 + d4.z * uu.z, y3 + d4.w * uu.w);
    }
}

// ============================================================================
extern "C" void kernel_launch(void* const* d_in, const int* in_sizes, int n_in,
                              void* d_out, int out_size)
{
    const float* u     = (const float*)d_in[0];
    const float* C_re  = (const float*)d_in[1];
    const float* C_im  = (const float*)d_in[2];
    const float* B_re  = (const float*)d_in[3];
    const float* B_im  = (const float*)d_in[4];
    const float* D     = (const float*)d_in[5];
    const float* nu    = (const float*)d_in[6];
    const float* theta = (const float*)d_in[7];
    const float* gamma = (const float*)d_in[8];
    float* out = (float*)d_out;

    dim3 gGrid(NN / 64, MTOT / 128);            // (8, 128)
    gemm1_kernel<<<gGrid, 256>>>(u, B_re, B_im, gamma);
    scan_local_kernel<<<dim3(NCHUNK, NBATCH), NN>>>(nu, theta);
    scan_chunk_kernel<<<NBATCH, NN>>>(nu, theta);
    scan_fix_kernel<<<dim3(NCHUNK - 1, NBATCH), NN>>>(nu, theta);
    gemm2_kernel<<<gGrid, 256>>>(C_re, C_im, u, D, out);
}

// round 7
// speedup vs baseline: 1.5897x; 1.5897x over previous
#include <cuda_runtime.h>
#include <cuda_bf16.h>
#include <cstdint>

// Problem dims
#define MTOT   16384      // BATCH*T = 8*2048
#define NN     512
#define TSEQ   2048
#define NBATCH 8
#define NCHUNK 64
#define CHUNKT 32

// ---------------- scratch (__device__ globals; no allocs allowed) -----------
__device__ float g_xre[(size_t)MTOT * NN];
__device__ float g_xim[(size_t)MTOT * NN];
__device__ float g_cre[NBATCH * NCHUNK * NN];
__device__ float g_cim[NBATCH * NCHUNK * NN];
__device__ float g_pre[NBATCH * NCHUNK * NN];
__device__ float g_pim[NBATCH * NCHUNK * NN];

// Pre-transposed, gamma-folded, bf16-split B panels (col-major for mma row.col)
// g_B1: [1024 n'][512 k]  rows 0-511 = (gamma*B_re) cols, 512-1023 = (gamma*B_im)
// g_B2: [512 n][1024 k]   k<512: C_re[k][n], k>=512: -C_im[k-512][n]
__device__ __nv_bfloat16 g_B1hi[1024 * 512];
__device__ __nv_bfloat16 g_B1lo[1024 * 512];
__device__ __nv_bfloat16 g_B2hi[512 * 1024];
__device__ __nv_bfloat16 g_B2lo[512 * 1024];

// ---------------- helpers ---------------------------------------------------
__device__ __forceinline__ uint32_t smem_u32(const void* p) {
    uint32_t a;
    asm("{ .reg .u64 t; cvta.to.shared.u64 t, %1; cvt.u32.u64 %0, t; }"
        : "=r"(a) : "l"(p));
    return a;
}

__device__ __forceinline__ void ldsm4(uint32_t* r, uint32_t addr) {
    asm volatile("ldmatrix.sync.aligned.m8n8.x4.shared.b16 {%0,%1,%2,%3}, [%4];"
        : "=r"(r[0]), "=r"(r[1]), "=r"(r[2]), "=r"(r[3]) : "r"(addr));
}

__device__ __forceinline__ void mma_bf16(float* c, const uint32_t* a, const uint32_t* b) {
    asm volatile("mma.sync.aligned.m16n8k16.row.col.f32.bf16.bf16.f32 "
        "{%0,%1,%2,%3}, {%4,%5,%6,%7}, {%8,%9}, {%0,%1,%2,%3};"
        : "+f"(c[0]), "+f"(c[1]), "+f"(c[2]), "+f"(c[3])
        : "r"(a[0]), "r"(a[1]), "r"(a[2]), "r"(a[3]), "r"(b[0]), "r"(b[1]));
}

__device__ __forceinline__ void split2(float v, unsigned short& hb, unsigned short& lb) {
    __nv_bfloat16 h = __float2bfloat16(v);
    float r = v - __bfloat162float(h);
    __nv_bfloat16 l = __float2bfloat16(r);
    hb = *reinterpret_cast<unsigned short*>(&h);
    lb = *reinterpret_cast<unsigned short*>(&l);
}

// ============================================================================
// Prep: transpose + gamma-fold + bf16 split of the 4 weight matrices
// ============================================================================
__global__ void prep_kernel(const float* __restrict__ Bre, const float* __restrict__ Bim,
                            const float* __restrict__ Cre, const float* __restrict__ Cim,
                            const float* __restrict__ gamma)
{
    __shared__ float tile[32][33];
    const int z = blockIdx.z;
    const float* S = (z == 0) ? Bre : (z == 1) ? Bim : (z == 2) ? Cre : Cim;
    const int k0 = blockIdx.x * 32, n0 = blockIdx.y * 32;
    const int tx = threadIdx.x, ty = threadIdx.y;  // 32 x 8
#pragma unroll
    for (int i = 0; i < 32; i += 8)
        tile[ty + i][tx] = S[(size_t)(k0 + ty + i) * 512 + n0 + tx];
    __syncthreads();
#pragma unroll
    for (int i = 0; i < 32; i += 8) {
        int n = n0 + ty + i, k = k0 + tx;
        float v = tile[tx][ty + i];
        if (z < 2)  v *= gamma[k];
        if (z == 3) v = -v;
        unsigned short hb, lb;
        split2(v, hb, lb);
        __nv_bfloat16 h = *reinterpret_cast<__nv_bfloat16*>(&hb);
        __nv_bfloat16 l = *reinterpret_cast<__nv_bfloat16*>(&lb);
        if (z == 0) { g_B1hi[(size_t)n * 512 + k] = h;          g_B1lo[(size_t)n * 512 + k] = l; }
        if (z == 1) { g_B1hi[(size_t)(512 + n) * 512 + k] = h;  g_B1lo[(size_t)(512 + n) * 512 + k] = l; }
        if (z == 2) { g_B2hi[(size_t)n * 1024 + k] = h;         g_B2lo[(size_t)n * 1024 + k] = l; }
        if (z == 3) { g_B2hi[(size_t)n * 1024 + 512 + k] = h;   g_B2lo[(size_t)n * 1024 + 512 + k] = l; }
    }
}

// ============================================================================
// HMMA GEMM, split-bf16 fp32 emulation (mma.sync m16n8k16 bf16).
// mode 0: D[16384,1024] = u @ B1^T           -> writes g_xre / g_xim
// mode 1: D[16384, 512] = [x_re|x_im] @ B2^T -> out = D + Dvec*u
// CTA tile M=128 N=128 K=32; 8 warps (warp tile 32x64); double-buffered smem.
// smem row layout (A and B identical): 128 rows x 128B, row = 32 hi bf16 then
// 32 lo bf16, 16B chunk c stored at (c ^ (row&7)) for conflict-free ldmatrix.
// ============================================================================
#define STAGE_BYTES 32768
#define SMEM_TOTAL  (2 * STAGE_BYTES)

__global__ __launch_bounds__(256, 1)
void gemm_tc(int mode, int kch, const float* __restrict__ u,
             const float* __restrict__ Dvec, float* __restrict__ out)
{
    extern __shared__ __align__(1024) char smem[];
    const int tid = threadIdx.x;
    const int lane = tid & 31, wid = tid >> 5;
    const int wm = wid >> 1, wn = wid & 1;      // 4 m-warps x 2 n-warps
    const int nBase = blockIdx.x * 128, mBase = blockIdx.y * 128;
    const uint32_t sb = smem_u32(smem);

    const __nv_bfloat16* Bh = mode ? g_B2hi : g_B1hi;
    const __nv_bfloat16* Bl = mode ? g_B2lo : g_B1lo;
    const int ldb = mode ? 1024 : 512;

    // loader mapping: 2 threads per row, each covers 16 k
    const int r = tid >> 1, half = tid & 1;
    const int swz = r & 7;

    // ldmatrix lane mapping
    const int g = lane >> 3, lr = lane & 7;
    int aRow[2], bRow[4];
#pragma unroll
    for (int mf = 0; mf < 2; mf++) aRow[mf] = wm * 32 + mf * 16 + (g & 1) * 8 + lr;
#pragma unroll
    for (int np = 0; np < 4; np++) bRow[np] = wn * 64 + np * 16 + (g >> 1) * 8 + lr;
    const int aCk = g >> 1;      // A chunk offset from lane group
    const int bCk = g & 1;       // B chunk offset

    float acc[2][8][4];
#pragma unroll
    for (int i = 0; i < 2; i++)
#pragma unroll
        for (int j = 0; j < 8; j++)
#pragma unroll
            for (int q = 0; q < 4; q++) acc[i][j][q] = 0.f;

    float4 aR[4];
    uint4  bR[4];

    auto LDG = [&](int c) {
        const float* Asrc; int kk0;
        if (mode == 0)      { Asrc = u;     kk0 = c * 32; }
        else if (c < 16)    { Asrc = g_xre; kk0 = c * 32; }
        else                { Asrc = g_xim; kk0 = (c - 16) * 32; }
        const float* ap = Asrc + (size_t)(mBase + r) * 512 + kk0 + half * 16;
        aR[0] = *(const float4*)(ap + 0);
        aR[1] = *(const float4*)(ap + 4);
        aR[2] = *(const float4*)(ap + 8);
        aR[3] = *(const float4*)(ap + 12);
        const __nv_bfloat16* bph = Bh + (size_t)(nBase + r) * ldb + c * 32 + half * 16;
        const __nv_bfloat16* bpl = Bl + (size_t)(nBase + r) * ldb + c * 32 + half * 16;
        bR[0] = *(const uint4*)(bph);
        bR[1] = *(const uint4*)(bph + 8);
        bR[2] = *(const uint4*)(bpl);
        bR[3] = *(const uint4*)(bpl + 8);
    };

    auto STS = [&](int s) {
        char* bufA = smem + s * STAGE_BYTES;
        char* bufB = bufA + 16384;
        float f[16] = {aR[0].x, aR[0].y, aR[0].z, aR[0].w,
                       aR[1].x, aR[1].y, aR[1].z, aR[1].w,
                       aR[2].x, aR[2].y, aR[2].z, aR[2].w,
                       aR[3].x, aR[3].y, aR[3].z, aR[3].w};
        uint32_t hw[8], lw[8];
#pragma unroll
        for (int j = 0; j < 8; j++) {
            unsigned short h0, l0, h1, l1;
            split2(f[2 * j], h0, l0);
            split2(f[2 * j + 1], h1, l1);
            hw[j] = (uint32_t)h0 | ((uint32_t)h1 << 16);
            lw[j] = (uint32_t)l0 | ((uint32_t)l1 << 16);
        }
        char* rowA = bufA + r * 128;
        *(uint4*)(rowA + (((half * 2 + 0) ^ swz) << 4)) = make_uint4(hw[0], hw[1], hw[2], hw[3]);
        *(uint4*)(rowA + (((half * 2 + 1) ^ swz) << 4)) = make_uint4(hw[4], hw[5], hw[6], hw[7]);
        *(uint4*)(rowA + (((4 + half * 2 + 0) ^ swz) << 4)) = make_uint4(lw[0], lw[1], lw[2], lw[3]);
        *(uint4*)(rowA + (((4 + half * 2 + 1) ^ swz) << 4)) = make_uint4(lw[4], lw[5], lw[6], lw[7]);
        char* rowB = bufB + r * 128;
        *(uint4*)(rowB + (((half * 2 + 0) ^ swz) << 4)) = bR[0];
        *(uint4*)(rowB + (((half * 2 + 1) ^ swz) << 4)) = bR[1];
        *(uint4*)(rowB + (((4 + half * 2 + 0) ^ swz) << 4)) = bR[2];
        *(uint4*)(rowB + (((4 + half * 2 + 1) ^ swz) << 4)) = bR[3];
    };

    auto COMPUTE = [&](int s) {
        const uint32_t baseA = sb + s * STAGE_BYTES;
        const uint32_t baseB = baseA + 16384;
#pragma unroll
        for (int ks = 0; ks < 2; ks++) {
            uint32_t ah[2][4], al[2][4];
#pragma unroll
            for (int mf = 0; mf < 2; mf++) {
                const int rw = aRow[mf];
                ldsm4(ah[mf], baseA + rw * 128 + (((ks * 2 + aCk) ^ (rw & 7)) << 4));
                ldsm4(al[mf], baseA + rw * 128 + (((4 + ks * 2 + aCk) ^ (rw & 7)) << 4));
            }
            uint32_t bh[4][4], bl[4][4];
#pragma unroll
            for (int np = 0; np < 4; np++) {
                const int rw = bRow[np];
                ldsm4(bh[np], baseB + rw * 128 + (((ks * 2 + bCk) ^ (rw & 7)) << 4));
                ldsm4(bl[np], baseB + rw * 128 + (((4 + ks * 2 + bCk) ^ (rw & 7)) << 4));
            }
#pragma unroll
            for (int mf = 0; mf < 2; mf++)
#pragma unroll
                for (int np = 0; np < 4; np++) {
                    mma_bf16(acc[mf][2 * np],     ah[mf], &bh[np][0]);
                    mma_bf16(acc[mf][2 * np + 1], ah[mf], &bh[np][2]);
                    mma_bf16(acc[mf][2 * np],     ah[mf], &bl[np][0]);
                    mma_bf16(acc[mf][2 * np + 1], ah[mf], &bl[np][2]);
                    mma_bf16(acc[mf][2 * np],     al[mf], &bh[np][0]);
                    mma_bf16(acc[mf][2 * np + 1], al[mf], &bh[np][2]);
                }
        }
    };

    LDG(0);
    STS(0);
    __syncthreads();
    for (int c = 0; c < kch; c++) {
        if (c + 1 < kch) LDG(c + 1);
        COMPUTE(c & 1);
        if (c + 1 < kch) {
            __syncthreads();
            STS((c + 1) & 1);
            __syncthreads();
        }
    }

    // ---- epilogue: write accumulators ----
    const int em = lane >> 2, en = (lane & 3) * 2;
#pragma unroll
    for (int mf = 0; mf < 2; mf++)
#pragma unroll
        for (int nf = 0; nf < 8; nf++) {
            const int m = mBase + wm * 32 + mf * 16 + em;
            const int n = nBase + wn * 64 + nf * 8 + en;
            const float* a4 = acc[mf][nf];
            if (mode == 0) {
                float* dst = (n < 512) ? g_xre : g_xim;
                const int nc = n & 511;
                *(float2*)&dst[(size_t)m * 512 + nc]       = make_float2(a4[0], a4[1]);
                *(float2*)&dst[(size_t)(m + 8) * 512 + nc] = make_float2(a4[2], a4[3]);
            } else {
                float2 dd = *(const float2*)&Dvec[n];
                float2 u0 = *(const float2*)&u[(size_t)m * 512 + n];
                float2 u1 = *(const float2*)&u[(size_t)(m + 8) * 512 + n];
                *(float2*)&out[(size_t)m * 512 + n] =
                    make_float2(a4[0] + dd.x * u0.x, a4[1] + dd.y * u0.y);
                *(float2*)&out[(size_t)(m + 8) * 512 + n] =
                    make_float2(a4[2] + dd.x * u1.x, a4[3] + dd.y * u1.y);
            }
        }
}

// ============================================================================
// Scan (3-phase chunked): x[t] = lam*x[t-1] + new_u[t], in place over g_x*
// ============================================================================
__global__ __launch_bounds__(512) void scan_local_kernel(
    const float* __restrict__ nu, const float* __restrict__ theta)
{
    const int n = threadIdx.x;
    const int c = blockIdx.x;
    const int b = blockIdx.y;
    const float r = expf(-expf(nu[n]));
    const float th = theta[n];
    const float lre = r * cosf(th), lim = r * sinf(th);
    float xr = 0.f, xi = 0.f;
    size_t base = ((size_t)(b * TSEQ + c * CHUNKT)) * NN + n;
#pragma unroll 4
    for (int t = 0; t < CHUNKT; t++) {
        size_t idx = base + (size_t)t * NN;
        float ur = g_xre[idx], ui = g_xim[idx];
        float nr = lre * xr - lim * xi + ur;
        float ni = lre * xi + lim * xr + ui;
        xr = nr; xi = ni;
        g_xre[idx] = xr; g_xim[idx] = xi;
    }
    int coff = (b * NCHUNK + c) * NN + n;
    g_cre[coff] = xr; g_cim[coff] = xi;
}

__global__ __launch_bounds__(512) void scan_chunk_kernel(
    const float* __restrict__ nu, const float* __restrict__ theta)
{
    const int n = threadIdx.x;
    const int b = blockIdx.x;
    const float e = expf(nu[n]);
    const float rP = expf(-(float)CHUNKT * e);
    const float ang = (float)CHUNKT * theta[n];
    const float Lre = rP * cosf(ang), Lim = rP * sinf(ang);
    float pr = 0.f, pi = 0.f;
#pragma unroll 4
    for (int c = 0; c < NCHUNK; c++) {
        int off = (b * NCHUNK + c) * NN + n;
        float cr = g_cre[off], ci = g_cim[off];
        float nr = Lre * pr - Lim * pi + cr;
        float ni = Lre * pi + Lim * pr + ci;
        pr = nr; pi = ni;
        g_pre[off] = pr; g_pim[off] = pi;
    }
}

__global__ __launch_bounds__(512) void scan_fix_kernel(
    const float* __restrict__ nu, const float* __restrict__ theta)
{
    const int n = threadIdx.x;
    const int c = blockIdx.x + 1;
    const int b = blockIdx.y;
    const float r = expf(-expf(nu[n]));
    const float th = theta[n];
    const float lre = r * cosf(th), lim = r * sinf(th);
    int poff = (b * NCHUNK + (c - 1)) * NN + n;
    float mr = g_pre[poff], mi = g_pim[poff];
    size_t base = ((size_t)(b * TSEQ + c * CHUNKT)) * NN + n;
#pragma unroll 4
    for (int t = 0; t < CHUNKT; t++) {
        float tr = lre * mr - lim * mi;
        float ti = lre * mi + lim * mr;
        mr = tr; mi = ti;
        size_t idx = base + (size_t)t * NN;
        g_xre[idx] += mr;
        g_xim[idx] += mi;
    }
}

// ============================================================================
extern "C" void kernel_launch(void* const* d_in, const int* in_sizes, int n_in,
                              void* d_out, int out_size)
{
    const float* u     = (const float*)d_in[0];
    const float* C_re  = (const float*)d_in[1];
    const float* C_im  = (const float*)d_in[2];
    const float* B_re  = (const float*)d_in[3];
    const float* B_im  = (const float*)d_in[4];
    const float* D     = (const float*)d_in[5];
    const float* nu    = (const float*)d_in[6];
    const float* theta = (const float*)d_in[7];
    const float* gamma = (const float*)d_in[8];
    float* out = (float*)d_out;

    cudaFuncSetAttribute(gemm_tc, cudaFuncAttributeMaxDynamicSharedMemorySize, SMEM_TOTAL);

    prep_kernel<<<dim3(16, 16, 4), dim3(32, 8)>>>(B_re, B_im, C_re, C_im, gamma);
    gemm_tc<<<dim3(8, 128), 256, SMEM_TOTAL>>>(0, 16, u, D, out);
    scan_local_kernel<<<dim3(NCHUNK, NBATCH), NN>>>(nu, theta);
    scan_chunk_kernel<<<NBATCH, NN>>>(nu, theta);
    scan_fix_kernel<<<dim3(NCHUNK - 1, NBATCH), NN>>>(nu, theta);
    gemm_tc<<<dim3(4, 128), 256, SMEM_TOTAL>>>(1, 32, u, D, out);
}